// round 1
// baseline (speedup 1.0000x reference)
#include <cuda_runtime.h>
#include <math.h>

#define KN 32
#define KC 64
#define KT 400
#define KV 27
#define KS 2

// ---------------- device scratch (no runtime allocation allowed) ----------------
__device__ float g_part[10 * KN * KS * KV * KV];   // per-chunk Gram partials
__device__ float g_att [KN * KS * KV * KV];        // final attention
__device__ float g_y4  [KN * KC * KT * KV];        // intermediate after ff stage (~88MB)

__device__ __forceinline__ float lrelu(float x) { return x > 0.f ? x : 0.1f * x; }

#define GFMA8(wa, wb, yv) do { \
  acc[0].x += (wa).x*(yv).x; acc[0].y += (wa).x*(yv).y; acc[0].z += (wa).x*(yv).z; acc[0].w += (wa).x*(yv).w; \
  acc[1].x += (wa).y*(yv).x; acc[1].y += (wa).y*(yv).y; acc[1].z += (wa).y*(yv).z; acc[1].w += (wa).y*(yv).w; \
  acc[2].x += (wa).z*(yv).x; acc[2].y += (wa).z*(yv).y; acc[2].z += (wa).z*(yv).z; acc[2].w += (wa).z*(yv).w; \
  acc[3].x += (wa).w*(yv).x; acc[3].y += (wa).w*(yv).y; acc[3].z += (wa).w*(yv).z; acc[3].w += (wa).w*(yv).w; \
  acc[4].x += (wb).x*(yv).x; acc[4].y += (wb).x*(yv).y; acc[4].z += (wb).x*(yv).z; acc[4].w += (wb).x*(yv).w; \
  acc[5].x += (wb).y*(yv).x; acc[5].y += (wb).y*(yv).y; acc[5].z += (wb).y*(yv).z; acc[5].w += (wb).y*(yv).w; \
  acc[6].x += (wb).z*(yv).x; acc[6].y += (wb).z*(yv).y; acc[6].z += (wb).z*(yv).z; acc[6].w += (wb).z*(yv).w; \
  acc[7].x += (wb).w*(yv).x; acc[7].y += (wb).w*(yv).y; acc[7].z += (wb).w*(yv).z; acc[7].w += (wb).w*(yv).w; \
} while (0)

// ============================================================================
// Kernel A: attention Gram logits.  Per block: one (n, s, chunk-of-40-t).
// QK = W_qk @ (x+pe) as 32x108x64 GEMM per 4-t group; accumulate
// G[u][v] += sum_{c,t} Q[c,t,u] K[c,t,v] in registers; write chunk partial.
// smem floats: WQKT [64][32] @0 | BQK[32] @2048 | Ys [64][108] @2080 | QKs [32][108] @8992
// total 12448 floats = 49792 B (dynamic)
// ============================================================================
__global__ void kA(const float* __restrict__ x, const float* __restrict__ pe,
                   const float* __restrict__ W_in, const float* __restrict__ b_in) {
  extern __shared__ float sm[];
  float* WQKT = sm;            // [cc][r]  r: 0..15 = q rows, 16..31 = k rows
  float* BQK  = sm + 2048;
  float* Ys   = sm + 2080;     // [cc][u*4+tt]
  float* QKs  = sm + 8992;     // [r][u*4+tt]
  const int tid = threadIdx.x;
  const int chunk = blockIdx.x, s = blockIdx.y, n = blockIdx.z;

  for (int j = tid; j < 2048; j += 224) {
    int cc = j >> 5, r = j & 31;
    int row = (r < 16) ? (s * 16 + r) : (32 + s * 16 + (r - 16));
    WQKT[cc * 32 + r] = W_in[row * 64 + cc];
  }
  if (tid < 32) {
    int r = tid;
    int row = (r < 16) ? (s * 16 + r) : (32 + s * 16 + (r - 16));
    BQK[r] = b_in[row];
  }
  float g0 = 0.f, g1 = 0.f, g2 = 0.f, g3 = 0.f;
  __syncthreads();

  for (int grp = 0; grp < 10; ++grp) {
    const int t0 = chunk * 40 + grp * 4;
    for (int j = tid; j < 64 * 108; j += 224) {
      int cc = j / 108, r = j % 108;
      int tt = r / 27, u = r % 27;
      int t = t0 + tt;
      Ys[cc * 108 + u * 4 + tt] =
          x[((n * 64 + cc) * 400 + t) * 27 + u] + pe[(cc * 400 + t) * 27 + u];
    }
    __syncthreads();

    if (tid < 216) {
      const int rg = tid / 27, colg = tid % 27;
      float b0 = BQK[rg * 4 + 0], b1 = BQK[rg * 4 + 1], b2 = BQK[rg * 4 + 2], b3 = BQK[rg * 4 + 3];
      float4 a0 = make_float4(b0, b0, b0, b0);
      float4 a1 = make_float4(b1, b1, b1, b1);
      float4 a2 = make_float4(b2, b2, b2, b2);
      float4 a3 = make_float4(b3, b3, b3, b3);
      #pragma unroll 8
      for (int cc = 0; cc < 64; ++cc) {
        float4 w = *(const float4*)&WQKT[cc * 32 + rg * 4];
        float4 y = *(const float4*)&Ys[cc * 108 + colg * 4];
        a0.x += w.x * y.x; a0.y += w.x * y.y; a0.z += w.x * y.z; a0.w += w.x * y.w;
        a1.x += w.y * y.x; a1.y += w.y * y.y; a1.z += w.y * y.z; a1.w += w.y * y.w;
        a2.x += w.z * y.x; a2.y += w.z * y.y; a2.z += w.z * y.z; a2.w += w.z * y.w;
        a3.x += w.w * y.x; a3.y += w.w * y.y; a3.z += w.w * y.z; a3.w += w.w * y.w;
      }
      *(float4*)&QKs[(rg * 4 + 0) * 108 + colg * 4] = a0;
      *(float4*)&QKs[(rg * 4 + 1) * 108 + colg * 4] = a1;
      *(float4*)&QKs[(rg * 4 + 2) * 108 + colg * 4] = a2;
      *(float4*)&QKs[(rg * 4 + 3) * 108 + colg * 4] = a3;
    }
    __syncthreads();

    // Gram accumulation: pairs p = tid + 224*i
    #pragma unroll
    for (int ii = 0; ii < 4; ++ii) {
      int p = tid + 224 * ii;
      if (p < 729) {
        int u = p / 27, vv = p % 27;
        float acc = 0.f;
        #pragma unroll 4
        for (int c = 0; c < 16; ++c) {
          float4 q = *(const float4*)&QKs[c * 108 + u * 4];
          float4 k = *(const float4*)&QKs[(16 + c) * 108 + vv * 4];
          acc += q.x * k.x + q.y * k.y + q.z * k.z + q.w * k.w;
        }
        if (ii == 0) g0 += acc; else if (ii == 1) g1 += acc;
        else if (ii == 2) g2 += acc; else g3 += acc;
      }
    }
    __syncthreads();
  }

  const int base = (chunk * 64 + n * 2 + s) * 729;
  g_part[base + tid] = g0;
  g_part[base + tid + 224] = g1;
  g_part[base + tid + 448] = g2;
  if (tid + 672 < 729) g_part[base + tid + 672] = g3;
}

// ============================================================================
// Kernel B: reduce partials, tanh scale, alpha/att0.
// ============================================================================
__global__ void kB(const float* __restrict__ alphas, const float* __restrict__ att0) {
  int idx = blockIdx.x * 256 + threadIdx.x;
  if (idx >= KN * KS * 729) return;
  int ns = idx / 729, p = idx % 729;
  int s = ns & 1;
  float sum = 0.f;
  #pragma unroll
  for (int ch = 0; ch < 10; ++ch) sum += g_part[ch * 46656 + idx];
  g_att[idx] = tanhf(sum * (1.0f / 6400.0f)) * alphas[s] + att0[s * 729 + p];
}

// ============================================================================
// Kernel C: per (n, 4-t tile):
//   y2[sc, tv] = sum_u x[c,t,u] att[s,u,v]
//   y3 = lrelu(x + bn(W_out @ y2))
//   y4 = lrelu(x + bn(W_ff  @ y3))  -> g_y4
// smem float offsets:
//   WOUT [sc][o] 0..8192 | WFF [ci][o] 8192..12288 | ATT 12288..13746
//   CAO 13748 CBO 13812 CAF 13876 CBF 13940
//   XS [c][tt*27+v] 14004..20916 | Y2 [sc][v*4+tt] 20916..34740 | Y3 [o][v*4+tt] 34740..41652
// total 41652 floats = 166608 B
// ============================================================================
__global__ void kC(const float* __restrict__ x,
                   const float* __restrict__ W_out, const float* __restrict__ b_out,
                   const float* __restrict__ gm_out, const float* __restrict__ be_out,
                   const float* __restrict__ m_out, const float* __restrict__ v_out,
                   const float* __restrict__ W_ff, const float* __restrict__ b_ff,
                   const float* __restrict__ gm_ff, const float* __restrict__ be_ff,
                   const float* __restrict__ m_ff, const float* __restrict__ v_ff) {
  extern __shared__ float sm[];
  const int WOUT = 0, WFF = 8192, ATT = 12288;
  const int CAO = 13748, CBO = 13812, CAF = 13876, CBF = 13940;
  const int XS = 14004, Y2 = 20916, Y3 = 34740;
  const int tid = threadIdx.x;
  const int n = blockIdx.y;
  const int t0 = blockIdx.x * 4;

  for (int j = tid; j < 8192; j += 224) {
    int o = j >> 7, sc = j & 127;
    sm[WOUT + sc * 64 + o] = W_out[j];
  }
  for (int j = tid; j < 4096; j += 224) {
    int o = j >> 6, ci = j & 63;
    sm[WFF + ci * 64 + o] = W_ff[j];
  }
  for (int j = tid; j < 1458; j += 224) sm[ATT + j] = g_att[n * 1458 + j];
  if (tid < 64) {
    float a = gm_out[tid] * rsqrtf(v_out[tid] + 1e-5f);
    sm[CAO + tid] = a;
    sm[CBO + tid] = (b_out[tid] - m_out[tid]) * a + be_out[tid];
    float af = gm_ff[tid] * rsqrtf(v_ff[tid] + 1e-5f);
    sm[CAF + tid] = af;
    sm[CBF + tid] = (b_ff[tid] - m_ff[tid]) * af + be_ff[tid];
  }
  for (int j = tid; j < 6912; j += 224) {
    int c = j / 108, r = j % 108;
    sm[XS + j] = x[((n * 64 + c) * 400 + t0 + r / 27) * 27 + (r % 27)];
  }
  __syncthreads();

  // ---- y2 stage: thread = (s, v, c-quarter), att column in registers ----
  if (tid < 216) {
    int s = tid / 108, rr = tid % 108;
    int v = rr >> 2, cq = rr & 3;
    float attc[27];
    #pragma unroll
    for (int u = 0; u < 27; ++u) attc[u] = sm[ATT + s * 729 + u * 27 + v];
    int c0 = cq * 16;
    for (int ci = 0; ci < 16; ++ci) {
      int c = c0 + ci;
      const float* xr = &sm[XS + c * 108];
      float a0 = 0.f, a1 = 0.f, a2 = 0.f, a3 = 0.f;
      #pragma unroll
      for (int u = 0; u < 27; ++u) {
        float av = attc[u];
        a0 += xr[u] * av; a1 += xr[27 + u] * av;
        a2 += xr[54 + u] * av; a3 += xr[81 + u] * av;
      }
      *(float4*)&sm[Y2 + (s * 64 + c) * 108 + v * 4] = make_float4(a0, a1, a2, a3);
    }
  }
  __syncthreads();

  // ---- y3 stage: 64x108 GEMM, K=128, 8x4 register tile ----
  if (tid < 216) {
    const int og = tid / 27, v = tid % 27;
    float4 acc[8];
    #pragma unroll
    for (int j = 0; j < 8; ++j) acc[j] = make_float4(0.f, 0.f, 0.f, 0.f);
    #pragma unroll 4
    for (int sc = 0; sc < 128; ++sc) {
      float4 yv = *(const float4*)&sm[Y2 + sc * 108 + v * 4];
      float4 wa = *(const float4*)&sm[WOUT + sc * 64 + og * 8];
      float4 wb = *(const float4*)&sm[WOUT + sc * 64 + og * 8 + 4];
      GFMA8(wa, wb, yv);
    }
    #pragma unroll
    for (int j = 0; j < 8; ++j) {
      int o = og * 8 + j;
      float a = sm[CAO + o], b = sm[CBO + o];
      float x0 = sm[XS + o * 108 + 0 * 27 + v];
      float x1 = sm[XS + o * 108 + 1 * 27 + v];
      float x2 = sm[XS + o * 108 + 2 * 27 + v];
      float x3 = sm[XS + o * 108 + 3 * 27 + v];
      float r0 = lrelu(x0 + acc[j].x * a + b);
      float r1 = lrelu(x1 + acc[j].y * a + b);
      float r2 = lrelu(x2 + acc[j].z * a + b);
      float r3 = lrelu(x3 + acc[j].w * a + b);
      *(float4*)&sm[Y3 + o * 108 + v * 4] = make_float4(r0, r1, r2, r3);
    }
  }
  __syncthreads();

  // ---- y4 stage: 64x108 GEMM, K=64 ----
  if (tid < 216) {
    const int og = tid / 27, v = tid % 27;
    float4 acc[8];
    #pragma unroll
    for (int j = 0; j < 8; ++j) acc[j] = make_float4(0.f, 0.f, 0.f, 0.f);
    #pragma unroll 4
    for (int ci = 0; ci < 64; ++ci) {
      float4 yv = *(const float4*)&sm[Y3 + ci * 108 + v * 4];
      float4 wa = *(const float4*)&sm[WFF + ci * 64 + og * 8];
      float4 wb = *(const float4*)&sm[WFF + ci * 64 + og * 8 + 4];
      GFMA8(wa, wb, yv);
    }
    #pragma unroll
    for (int j = 0; j < 8; ++j) {
      int o = og * 8 + j;
      float a = sm[CAF + o], b = sm[CBF + o];
      float x0 = sm[XS + o * 108 + 0 * 27 + v];
      float x1 = sm[XS + o * 108 + 1 * 27 + v];
      float x2 = sm[XS + o * 108 + 2 * 27 + v];
      float x3 = sm[XS + o * 108 + 3 * 27 + v];
      long ob = ((long)(n * 64 + o) * 400 + t0) * 27 + v;
      g_y4[ob +  0] = lrelu(x0 + acc[j].x * a + b);
      g_y4[ob + 27] = lrelu(x1 + acc[j].y * a + b);
      g_y4[ob + 54] = lrelu(x2 + acc[j].z * a + b);
      g_y4[ob + 81] = lrelu(x3 + acc[j].w * a + b);
    }
  }
}

// ============================================================================
// Kernel D: temporal 3x1 conv + bn + residual + lrelu.
// Per (n, 4-t tile): output 64 x (4t x 27v), K = 64ch x 3tap.
// smem floats: WT [i][k][o] 0..12288 | YS [i][tloc(6)][v] 12288..22656 | CAT 22656 CBT 22720
// total 22784 floats = 91136 B
// ============================================================================
__global__ void kD(const float* __restrict__ W_t, const float* __restrict__ b_t,
                   const float* __restrict__ gm_t, const float* __restrict__ be_t,
                   const float* __restrict__ m_t, const float* __restrict__ v_t,
                   float* __restrict__ out) {
  extern __shared__ float sm[];
  const int WT = 0, YS = 12288, CAT = 22656, CBT = 22720;
  const int tid = threadIdx.x;
  const int n = blockIdx.y;
  const int t0 = blockIdx.x * 4;

  for (int j = tid; j < 12288; j += 224) {
    int o = j / 192, r = j % 192;
    int i = r / 3, k = r % 3;
    sm[WT + (i * 3 + k) * 64 + o] = W_t[j];
  }
  for (int j = tid; j < 10368; j += 224) {
    int i = j / 162, r = j % 162;
    int tl = r / 27, v = r % 27;
    int t = t0 - 1 + tl;
    sm[YS + j] = (t >= 0 && t < 400) ? g_y4[((n * 64 + i) * 400 + t) * 27 + v] : 0.f;
  }
  if (tid < 64) {
    float a = gm_t[tid] * rsqrtf(v_t[tid] + 1e-5f);
    sm[CAT + tid] = a;
    sm[CBT + tid] = (b_t[tid] - m_t[tid]) * a + be_t[tid];
  }
  __syncthreads();

  if (tid < 216) {
    const int og = tid / 27, v = tid % 27;
    float4 acc[8];
    #pragma unroll
    for (int j = 0; j < 8; ++j) acc[j] = make_float4(0.f, 0.f, 0.f, 0.f);
    #pragma unroll 2
    for (int i = 0; i < 64; ++i) {
      float yv6[6];
      #pragma unroll
      for (int tl = 0; tl < 6; ++tl) yv6[tl] = sm[YS + i * 162 + tl * 27 + v];
      #pragma unroll
      for (int k = 0; k < 3; ++k) {
        float4 wa = *(const float4*)&sm[WT + (i * 3 + k) * 64 + og * 8];
        float4 wb = *(const float4*)&sm[WT + (i * 3 + k) * 64 + og * 8 + 4];
        float4 yv = make_float4(yv6[k], yv6[k + 1], yv6[k + 2], yv6[k + 3]);
        GFMA8(wa, wb, yv);
      }
    }
    #pragma unroll
    for (int j = 0; j < 8; ++j) {
      int o = og * 8 + j;
      float a = sm[CAT + o], b = sm[CBT + o];
      float y0 = sm[YS + o * 162 + 1 * 27 + v];
      float y1 = sm[YS + o * 162 + 2 * 27 + v];
      float y2 = sm[YS + o * 162 + 3 * 27 + v];
      float y3 = sm[YS + o * 162 + 4 * 27 + v];
      long ob = ((long)(n * 64 + o) * 400 + t0) * 27 + v;
      out[ob +  0] = lrelu(y0 + acc[j].x * a + b);
      out[ob + 27] = lrelu(y1 + acc[j].y * a + b);
      out[ob + 54] = lrelu(y2 + acc[j].z * a + b);
      out[ob + 81] = lrelu(y3 + acc[j].w * a + b);
    }
  }
}

// ============================================================================
extern "C" void kernel_launch(void* const* d_in, const int* in_sizes, int n_in,
                              void* d_out, int out_size) {
  const float* x      = (const float*)d_in[0];
  const float* pe     = (const float*)d_in[1];
  const float* W_in   = (const float*)d_in[2];
  const float* b_in   = (const float*)d_in[3];
  const float* alphas = (const float*)d_in[4];
  const float* att0   = (const float*)d_in[5];
  const float* W_out  = (const float*)d_in[6];
  const float* b_out  = (const float*)d_in[7];
  const float* g_out  = (const float*)d_in[8];
  const float* be_out = (const float*)d_in[9];
  const float* m_out  = (const float*)d_in[10];
  const float* v_out  = (const float*)d_in[11];
  const float* W_ff   = (const float*)d_in[12];
  const float* b_ff   = (const float*)d_in[13];
  const float* g_ff   = (const float*)d_in[14];
  const float* be_ff  = (const float*)d_in[15];
  const float* m_ff   = (const float*)d_in[16];
  const float* v_ff   = (const float*)d_in[17];
  const float* W_t    = (const float*)d_in[18];
  const float* b_t    = (const float*)d_in[19];
  const float* g_t    = (const float*)d_in[20];
  const float* be_t   = (const float*)d_in[21];
  const float* m_t    = (const float*)d_in[22];
  const float* v_t    = (const float*)d_in[23];
  float* out = (float*)d_out;

  cudaFuncSetAttribute(kA, cudaFuncAttributeMaxDynamicSharedMemorySize, 49792);
  cudaFuncSetAttribute(kC, cudaFuncAttributeMaxDynamicSharedMemorySize, 166608);
  cudaFuncSetAttribute(kD, cudaFuncAttributeMaxDynamicSharedMemorySize, 91136);

  kA<<<dim3(10, 2, 32), 224, 49792>>>(x, pe, W_in, b_in);
  kB<<<(KN * KS * 729 + 255) / 256, 256>>>(alphas, att0);
  kC<<<dim3(100, 32), 224, 166608>>>(x, W_out, b_out, g_out, be_out, m_out, v_out,
                                     W_ff, b_ff, g_ff, be_ff, m_ff, v_ff);
  kD<<<dim3(100, 32), 224, 91136>>>(W_t, b_t, g_t, be_t, m_t, v_t, out);
}

// round 3
// speedup vs baseline: 1.0087x; 1.0087x over previous
#include <cuda_runtime.h>
#include <math.h>

#define KN 32
#define KC 64
#define KT 400
#define KV 27
#define KS 2

// ---------------- device scratch ----------------
__device__ float g_part[10 * KN * KS * KV * KV];
__device__ float g_att [KN * KS * KV * KV];
__device__ float g_y4  [KN * KC * KT * KV];

__device__ __forceinline__ float lrelu(float x) { return x > 0.f ? x : 0.1f * x; }

// 8x8 register tile FMA: 8 o-rows x two 4-col halves.
__device__ __forceinline__ void fma8x8(float4* acc, float4 wa, float4 wb,
                                       float4 y0, float4 y1) {
  float wr[8] = {wa.x, wa.y, wa.z, wa.w, wb.x, wb.y, wb.z, wb.w};
  #pragma unroll
  for (int i = 0; i < 8; ++i) {
    float m = wr[i];
    acc[2*i].x   += m * y0.x; acc[2*i].y   += m * y0.y;
    acc[2*i].z   += m * y0.z; acc[2*i].w   += m * y0.w;
    acc[2*i+1].x += m * y1.x; acc[2*i+1].y += m * y1.y;
    acc[2*i+1].z += m * y1.z; acc[2*i+1].w += m * y1.w;
  }
}

// ============================================================================
// Kernel A: attention Gram logits (unchanged from R1).
// ============================================================================
__global__ void kA(const float* __restrict__ x, const float* __restrict__ pe,
                   const float* __restrict__ W_in, const float* __restrict__ b_in) {
  extern __shared__ float sm[];
  float* WQKT = sm;
  float* BQK  = sm + 2048;
  float* Ys   = sm + 2080;
  float* QKs  = sm + 8992;
  const int tid = threadIdx.x;
  const int chunk = blockIdx.x, s = blockIdx.y, n = blockIdx.z;

  for (int j = tid; j < 2048; j += 224) {
    int cc = j >> 5, r = j & 31;
    int row = (r < 16) ? (s * 16 + r) : (32 + s * 16 + (r - 16));
    WQKT[cc * 32 + r] = W_in[row * 64 + cc];
  }
  if (tid < 32) {
    int r = tid;
    int row = (r < 16) ? (s * 16 + r) : (32 + s * 16 + (r - 16));
    BQK[r] = b_in[row];
  }
  float g0 = 0.f, g1 = 0.f, g2 = 0.f, g3 = 0.f;
  __syncthreads();

  for (int grp = 0; grp < 10; ++grp) {
    const int t0 = chunk * 40 + grp * 4;
    for (int j = tid; j < 64 * 108; j += 224) {
      int cc = j / 108, r = j % 108;
      int tt = r / 27, u = r % 27;
      int t = t0 + tt;
      Ys[cc * 108 + u * 4 + tt] =
          x[((n * 64 + cc) * 400 + t) * 27 + u] + pe[(cc * 400 + t) * 27 + u];
    }
    __syncthreads();

    if (tid < 216) {
      const int rg = tid / 27, colg = tid % 27;
      float b0 = BQK[rg * 4 + 0], b1 = BQK[rg * 4 + 1], b2 = BQK[rg * 4 + 2], b3 = BQK[rg * 4 + 3];
      float4 a0 = make_float4(b0, b0, b0, b0);
      float4 a1 = make_float4(b1, b1, b1, b1);
      float4 a2 = make_float4(b2, b2, b2, b2);
      float4 a3 = make_float4(b3, b3, b3, b3);
      #pragma unroll 8
      for (int cc = 0; cc < 64; ++cc) {
        float4 w = *(const float4*)&WQKT[cc * 32 + rg * 4];
        float4 y = *(const float4*)&Ys[cc * 108 + colg * 4];
        a0.x += w.x * y.x; a0.y += w.x * y.y; a0.z += w.x * y.z; a0.w += w.x * y.w;
        a1.x += w.y * y.x; a1.y += w.y * y.y; a1.z += w.y * y.z; a1.w += w.y * y.w;
        a2.x += w.z * y.x; a2.y += w.z * y.y; a2.z += w.z * y.z; a2.w += w.z * y.w;
        a3.x += w.w * y.x; a3.y += w.w * y.y; a3.z += w.w * y.z; a3.w += w.w * y.w;
      }
      *(float4*)&QKs[(rg * 4 + 0) * 108 + colg * 4] = a0;
      *(float4*)&QKs[(rg * 4 + 1) * 108 + colg * 4] = a1;
      *(float4*)&QKs[(rg * 4 + 2) * 108 + colg * 4] = a2;
      *(float4*)&QKs[(rg * 4 + 3) * 108 + colg * 4] = a3;
    }
    __syncthreads();

    #pragma unroll
    for (int ii = 0; ii < 4; ++ii) {
      int p = tid + 224 * ii;
      if (p < 729) {
        int u = p / 27, vv = p % 27;
        float acc = 0.f;
        #pragma unroll 4
        for (int c = 0; c < 16; ++c) {
          float4 q = *(const float4*)&QKs[c * 108 + u * 4];
          float4 k = *(const float4*)&QKs[(16 + c) * 108 + vv * 4];
          acc += q.x * k.x + q.y * k.y + q.z * k.z + q.w * k.w;
        }
        if (ii == 0) g0 += acc; else if (ii == 1) g1 += acc;
        else if (ii == 2) g2 += acc; else g3 += acc;
      }
    }
    __syncthreads();
  }

  const int base = (chunk * 64 + n * 2 + s) * 729;
  g_part[base + tid] = g0;
  g_part[base + tid + 224] = g1;
  g_part[base + tid + 448] = g2;
  if (tid + 672 < 729) g_part[base + tid + 672] = g3;
}

// ============================================================================
// Kernel B: reduce partials, tanh scale (unchanged).
// ============================================================================
__global__ void kB(const float* __restrict__ alphas, const float* __restrict__ att0) {
  int idx = blockIdx.x * 256 + threadIdx.x;
  if (idx >= KN * KS * 729) return;
  int ns = idx / 729, p = idx % 729;
  int s = ns & 1;
  float sum = 0.f;
  #pragma unroll
  for (int ch = 0; ch < 10; ++ch) sum += g_part[ch * 46656 + idx];
  g_att[idx] = tanhf(sum * (1.0f / 6400.0f)) * alphas[s] + att0[s * 729 + p];
}

// ============================================================================
// Kernel C: per (n, 8-t tile), v padded to 28, col = tt*28+v (224 cols).
//   y2(s-half) -> YB ; GEMM1 accumulate over 2 halves (W phase-loaded);
//   y3 epilogue -> YB ; GEMM2 (W_ff) ; y4 epilogue -> g_y4.
// smem floats: WB[64][64]@0 | ATT[2][27][28]@4096 | consts@5608 |
//              XS[64][224]@5864 | YB[64][224]@20200 | total 34536 f = 138144 B
// ============================================================================
__device__ __forceinline__ void kc_gemm64(const float* sm, int YB, int og, int cg,
                                          float4* acc) {
  #pragma unroll 4
  for (int k = 0; k < 64; ++k) {
    float4 wa = *(const float4*)&sm[k * 64 + og * 8];
    float4 wb = *(const float4*)&sm[k * 64 + og * 8 + 4];
    float4 y0 = *(const float4*)&sm[YB + k * 224 + cg * 4];
    float4 y1 = *(const float4*)&sm[YB + k * 224 + 112 + cg * 4];
    fma8x8(acc, wa, wb, y0, y1);
  }
}

__device__ __forceinline__ void kc_y2phase(float* sm, int ATT, int XS, int YB,
                                           int S, int vq, int cq) {
  float a0r[27], a1r[27];
  const int v0 = vq * 2, v1 = vq * 2 + 1;
  #pragma unroll
  for (int u = 0; u < 27; ++u) {
    a0r[u] = sm[ATT + S * 756 + u * 28 + v0];
    a1r[u] = sm[ATT + S * 756 + u * 28 + v1];
  }
  for (int ci = 0; ci < 4; ++ci) {
    const int c = cq * 4 + ci;
    const float* xr = &sm[XS + c * 224];
    #pragma unroll 2
    for (int tt = 0; tt < 8; ++tt) {
      float s0 = 0.f, s1 = 0.f;
      #pragma unroll
      for (int u = 0; u < 27; ++u) {
        float xv = xr[tt * 28 + u];
        s0 += xv * a0r[u]; s1 += xv * a1r[u];
      }
      sm[YB + c * 224 + tt * 28 + v0] = s0;
      sm[YB + c * 224 + tt * 28 + v1] = s1;
    }
  }
}

__global__ void __launch_bounds__(224, 1)
kC(const float* __restrict__ x,
   const float* __restrict__ W_out, const float* __restrict__ b_out,
   const float* __restrict__ gm_out, const float* __restrict__ be_out,
   const float* __restrict__ m_out, const float* __restrict__ v_out,
   const float* __restrict__ W_ff, const float* __restrict__ b_ff,
   const float* __restrict__ gm_ff, const float* __restrict__ be_ff,
   const float* __restrict__ m_ff, const float* __restrict__ v_ff) {
  extern __shared__ float sm[];
  const int ATT = 4096, CAO = 5608, CBO = 5672, CAF = 5736, CBF = 5800;
  const int XS = 5864, YB = 20200;
  const int tid = threadIdx.x;
  const int n = blockIdx.y;
  const int t0 = blockIdx.x * 8;

  // phase 0: loads
  for (int j = tid; j < 14336; j += 224) {
    int c = j / 224, col = j % 224, tt = col / 28, v = col % 28;
    sm[XS + j] = (v < 27) ? x[((n * 64 + c) * 400 + t0 + tt) * 27 + v] : 0.f;
  }
  for (int j = tid; j < 1512; j += 224) {
    int s = j / 756, r = j % 756, u = r / 28, v = r % 28;
    sm[ATT + j] = (v < 27) ? g_att[(n * 2 + s) * 729 + u * 27 + v] : 0.f;
  }
  for (int j = tid; j < 4096; j += 224) {
    int k = j >> 6, o = j & 63;
    sm[j] = W_out[o * 128 + k];          // W_out s=0 half, [k][o]
  }
  if (tid < 64) {
    float a = gm_out[tid] * rsqrtf(v_out[tid] + 1e-5f);
    sm[CAO + tid] = a;
    sm[CBO + tid] = (b_out[tid] - m_out[tid]) * a + be_out[tid];
    float af = gm_ff[tid] * rsqrtf(v_ff[tid] + 1e-5f);
    sm[CAF + tid] = af;
    sm[CBF + tid] = (b_ff[tid] - m_ff[tid]) * af + be_ff[tid];
  }
  __syncthreads();

  const int vq = tid / 16, cq = tid % 16;   // y2 mapping (vq 0..13, cq 0..15)
  const int og = tid / 28, cg = tid % 28;   // GEMM mapping
  float4 acc[16];
  #pragma unroll
  for (int i = 0; i < 16; ++i) acc[i] = make_float4(0.f, 0.f, 0.f, 0.f);

  // s = 0
  kc_y2phase(sm, ATT, XS, YB, 0, vq, cq);
  __syncthreads();
  kc_gemm64(sm, YB, og, cg, acc);
  __syncthreads();

  // s = 1: swap weight half + recompute y2
  for (int j = tid; j < 4096; j += 224) {
    int k = j >> 6, o = j & 63;
    sm[j] = W_out[o * 128 + 64 + k];
  }
  kc_y2phase(sm, ATT, XS, YB, 1, vq, cq);
  __syncthreads();
  kc_gemm64(sm, YB, og, cg, acc);
  __syncthreads();

  // epilogue 1: y3 -> YB ; load W_ff
  for (int j = tid; j < 4096; j += 224) {
    int k = j >> 6, o = j & 63;
    sm[j] = W_ff[o * 64 + k];
  }
  #pragma unroll
  for (int jo = 0; jo < 8; ++jo) {
    int o = og * 8 + jo;
    float a = sm[CAO + o], b = sm[CBO + o];
    #pragma unroll
    for (int h = 0; h < 2; ++h) {
      float4 A = acc[jo * 2 + h];
      int base = h * 112 + cg * 4;
      float r0 = lrelu(sm[XS + o * 224 + base + 0] + A.x * a + b);
      float r1 = lrelu(sm[XS + o * 224 + base + 1] + A.y * a + b);
      float r2 = lrelu(sm[XS + o * 224 + base + 2] + A.z * a + b);
      float r3 = lrelu(sm[XS + o * 224 + base + 3] + A.w * a + b);
      *(float4*)&sm[YB + o * 224 + base] = make_float4(r0, r1, r2, r3);
    }
  }
  #pragma unroll
  for (int i = 0; i < 16; ++i) acc[i] = make_float4(0.f, 0.f, 0.f, 0.f);
  __syncthreads();

  kc_gemm64(sm, YB, og, cg, acc);

  // epilogue 2: y4 -> global
  #pragma unroll
  for (int jo = 0; jo < 8; ++jo) {
    int o = og * 8 + jo;
    float a = sm[CAF + o], b = sm[CBF + o];
    #pragma unroll
    for (int h = 0; h < 2; ++h) {
      float4 A = acc[jo * 2 + h];
      int base = h * 112 + cg * 4;
      float rv[4] = {A.x, A.y, A.z, A.w};
      #pragma unroll
      for (int e = 0; e < 4; ++e) {
        int col = base + e;
        int tt = col / 28, v = col % 28;
        if (v < 27) {
          float r = lrelu(sm[XS + o * 224 + col] + rv[e] * a + b);
          g_y4[((long)(n * 64 + o) * 400 + t0 + tt) * 27 + v] = r;
        }
      }
    }
  }
}

// ============================================================================
// Kernel D: temporal 3x1 conv + bn + res + lrelu, per (n, 8-t tile).
// smem floats: WT[192][64]@0 (12288) | YS[64][280]@12288 (17920) |
//              CAT@30208 CBT@30272 | total 30336 f = 121344 B
// ============================================================================
__global__ void __launch_bounds__(224, 1)
kD(const float* __restrict__ W_t, const float* __restrict__ b_t,
   const float* __restrict__ gm_t, const float* __restrict__ be_t,
   const float* __restrict__ m_t, const float* __restrict__ v_t,
   float* __restrict__ out) {
  extern __shared__ float sm[];
  const int YS = 12288, CAT = 30208, CBT = 30272;
  const int tid = threadIdx.x;
  const int n = blockIdx.y;
  const int t0 = blockIdx.x * 8;

  for (int j = tid; j < 12288; j += 224) {
    int o = j / 192, r = j % 192;        // r = i*3+kk
    sm[r * 64 + o] = W_t[j];
  }
  for (int j = tid; j < 17920; j += 224) {
    int i = j / 280, r = j % 280, tl = r / 28, v = r % 28;
    int t = t0 - 1 + tl;
    sm[YS + j] = (v < 27 && t >= 0 && t < 400)
                 ? g_y4[((long)(n * 64 + i) * 400 + t) * 27 + v] : 0.f;
  }
  if (tid < 64) {
    float a = gm_t[tid] * rsqrtf(v_t[tid] + 1e-5f);
    sm[CAT + tid] = a;
    sm[CBT + tid] = (b_t[tid] - m_t[tid]) * a + be_t[tid];
  }
  __syncthreads();

  const int og = tid / 28, cg = tid % 28;
  float4 acc[16];
  #pragma unroll
  for (int i = 0; i < 16; ++i) acc[i] = make_float4(0.f, 0.f, 0.f, 0.f);

  #pragma unroll 2
  for (int i = 0; i < 64; ++i) {
    #pragma unroll
    for (int kk = 0; kk < 3; ++kk) {
      float4 wa = *(const float4*)&sm[(i * 3 + kk) * 64 + og * 8];
      float4 wb = *(const float4*)&sm[(i * 3 + kk) * 64 + og * 8 + 4];
      float4 y0 = *(const float4*)&sm[YS + i * 280 + kk * 28 + cg * 4];
      float4 y1 = *(const float4*)&sm[YS + i * 280 + kk * 28 + 112 + cg * 4];
      fma8x8(acc, wa, wb, y0, y1);
    }
  }

  #pragma unroll
  for (int jo = 0; jo < 8; ++jo) {
    int o = og * 8 + jo;
    float a = sm[CAT + o], b = sm[CBT + o];
    #pragma unroll
    for (int h = 0; h < 2; ++h) {
      float4 A = acc[jo * 2 + h];
      int base = h * 112 + cg * 4;
      float rv[4] = {A.x, A.y, A.z, A.w};
      #pragma unroll
      for (int e = 0; e < 4; ++e) {
        int col = base + e;
        int tt = col / 28, v = col % 28;
        if (v < 27) {
          float y = sm[YS + o * 280 + (tt + 1) * 28 + v];   // residual y4
          float r = lrelu(y + rv[e] * a + b);
          out[((long)(n * 64 + o) * 400 + t0 + tt) * 27 + v] = r;
        }
      }
    }
  }
}

// ============================================================================
extern "C" void kernel_launch(void* const* d_in, const int* in_sizes, int n_in,
                              void* d_out, int out_size) {
  const float* x      = (const float*)d_in[0];
  const float* pe     = (const float*)d_in[1];
  const float* W_in   = (const float*)d_in[2];
  const float* b_in   = (const float*)d_in[3];
  const float* alphas = (const float*)d_in[4];
  const float* att0   = (const float*)d_in[5];
  const float* W_out  = (const float*)d_in[6];
  const float* b_out  = (const float*)d_in[7];
  const float* g_out  = (const float*)d_in[8];
  const float* be_out = (const float*)d_in[9];
  const float* m_out  = (const float*)d_in[10];
  const float* v_out  = (const float*)d_in[11];
  const float* W_ff   = (const float*)d_in[12];
  const float* b_ff   = (const float*)d_in[13];
  const float* g_ff   = (const float*)d_in[14];
  const float* be_ff  = (const float*)d_in[15];
  const float* m_ff   = (const float*)d_in[16];
  const float* v_ff   = (const float*)d_in[17];
  const float* W_t    = (const float*)d_in[18];
  const float* b_t    = (const float*)d_in[19];
  const float* g_t    = (const float*)d_in[20];
  const float* be_t   = (const float*)d_in[21];
  const float* m_t    = (const float*)d_in[22];
  const float* v_t    = (const float*)d_in[23];
  float* out = (float*)d_out;

  cudaFuncSetAttribute(kA, cudaFuncAttributeMaxDynamicSharedMemorySize, 49792);
  cudaFuncSetAttribute(kC, cudaFuncAttributeMaxDynamicSharedMemorySize, 138144);
  cudaFuncSetAttribute(kD, cudaFuncAttributeMaxDynamicSharedMemorySize, 121344);

  kA<<<dim3(10, 2, 32), 224, 49792>>>(x, pe, W_in, b_in);
  kB<<<(KN * KS * 729 + 255) / 256, 256>>>(alphas, att0);
  kC<<<dim3(50, 32), 224, 138144>>>(x, W_out, b_out, g_out, be_out, m_out, v_out,
                                    W_ff, b_ff, g_ff, be_ff, m_ff, v_ff);
  kD<<<dim3(50, 32), 224, 121344>>>(W_t, b_t, g_t, be_t, m_t, v_t, out);
}

// round 4
// speedup vs baseline: 1.1871x; 1.1768x over previous
#include <cuda_runtime.h>
#include <math.h>

#define KN 32
#define KC 64
#define KT 400
#define KV 27
#define KS 2

typedef unsigned long long u64;

// ---------------- device scratch ----------------
__device__ float g_part[20 * KN * KS * KV * KV];
__device__ float g_att [KN * KS * KV * KV];
__device__ float g_y4  [KN * KC * KT * KV];

__device__ __forceinline__ float lrelu(float x) { return x > 0.f ? x : 0.1f * x; }

// packed f32x2 helpers (FFMA2 path — only reachable via PTX)
__device__ __forceinline__ void ffma2(u64& d, u64 a, u64 b) {
  asm("fma.rn.f32x2 %0, %1, %2, %0;" : "+l"(d) : "l"(a), "l"(b));
}
__device__ __forceinline__ u64 bcast2(float w) {
  u64 r; asm("mov.b64 %0, {%1, %1};" : "=l"(r) : "f"(w)); return r;
}
__device__ __forceinline__ float2 unpk(u64 v) {
  float2 f; asm("mov.b64 {%0, %1}, %2;" : "=f"(f.x), "=f"(f.y) : "l"(v)); return f;
}

// ============================================================================
// Kernel A: attention Gram logits. Per block: (n, s, 20-t chunk), 5 groups of 4t.
// ============================================================================
__global__ void kA(const float* __restrict__ x, const float* __restrict__ pe,
                   const float* __restrict__ W_in, const float* __restrict__ b_in) {
  extern __shared__ float sm[];
  float* WQKT = sm;
  float* BQK  = sm + 2048;
  float* Ys   = sm + 2080;
  float* QKs  = sm + 8992;
  const int tid = threadIdx.x;
  const int chunk = blockIdx.x, s = blockIdx.y, n = blockIdx.z;

  for (int j = tid; j < 2048; j += 224) {
    int cc = j >> 5, r = j & 31;
    int row = (r < 16) ? (s * 16 + r) : (32 + s * 16 + (r - 16));
    WQKT[cc * 32 + r] = W_in[row * 64 + cc];
  }
  if (tid < 32) {
    int r = tid;
    int row = (r < 16) ? (s * 16 + r) : (32 + s * 16 + (r - 16));
    BQK[r] = b_in[row];
  }
  float g0 = 0.f, g1 = 0.f, g2 = 0.f, g3 = 0.f;
  __syncthreads();

  for (int grp = 0; grp < 5; ++grp) {
    const int t0 = chunk * 20 + grp * 4;
    for (int j = tid; j < 64 * 108; j += 224) {
      int cc = j / 108, r = j % 108;
      int tt = r / 27, u = r % 27;
      int t = t0 + tt;
      Ys[cc * 108 + u * 4 + tt] =
          x[((n * 64 + cc) * 400 + t) * 27 + u] + pe[(cc * 400 + t) * 27 + u];
    }
    __syncthreads();

    if (tid < 216) {
      const int rg = tid / 27, colg = tid % 27;
      float b0 = BQK[rg * 4 + 0], b1 = BQK[rg * 4 + 1], b2 = BQK[rg * 4 + 2], b3 = BQK[rg * 4 + 3];
      float4 a0 = make_float4(b0, b0, b0, b0);
      float4 a1 = make_float4(b1, b1, b1, b1);
      float4 a2 = make_float4(b2, b2, b2, b2);
      float4 a3 = make_float4(b3, b3, b3, b3);
      #pragma unroll 8
      for (int cc = 0; cc < 64; ++cc) {
        float4 w = *(const float4*)&WQKT[cc * 32 + rg * 4];
        float4 y = *(const float4*)&Ys[cc * 108 + colg * 4];
        a0.x += w.x * y.x; a0.y += w.x * y.y; a0.z += w.x * y.z; a0.w += w.x * y.w;
        a1.x += w.y * y.x; a1.y += w.y * y.y; a1.z += w.y * y.z; a1.w += w.y * y.w;
        a2.x += w.z * y.x; a2.y += w.z * y.y; a2.z += w.z * y.z; a2.w += w.z * y.w;
        a3.x += w.w * y.x; a3.y += w.w * y.y; a3.z += w.w * y.z; a3.w += w.w * y.w;
      }
      *(float4*)&QKs[(rg * 4 + 0) * 108 + colg * 4] = a0;
      *(float4*)&QKs[(rg * 4 + 1) * 108 + colg * 4] = a1;
      *(float4*)&QKs[(rg * 4 + 2) * 108 + colg * 4] = a2;
      *(float4*)&QKs[(rg * 4 + 3) * 108 + colg * 4] = a3;
    }
    __syncthreads();

    #pragma unroll
    for (int ii = 0; ii < 4; ++ii) {
      int p = tid + 224 * ii;
      if (p < 729) {
        int u = p / 27, vv = p % 27;
        float acc = 0.f;
        #pragma unroll 4
        for (int c = 0; c < 16; ++c) {
          float4 q = *(const float4*)&QKs[c * 108 + u * 4];
          float4 k = *(const float4*)&QKs[(16 + c) * 108 + vv * 4];
          acc += q.x * k.x + q.y * k.y + q.z * k.z + q.w * k.w;
        }
        if (ii == 0) g0 += acc; else if (ii == 1) g1 += acc;
        else if (ii == 2) g2 += acc; else g3 += acc;
      }
    }
    __syncthreads();
  }

  const int base = (chunk * 64 + n * 2 + s) * 729;
  g_part[base + tid] = g0;
  g_part[base + tid + 224] = g1;
  g_part[base + tid + 448] = g2;
  if (tid + 672 < 729) g_part[base + tid + 672] = g3;
}

// ============================================================================
// Kernel B: reduce 20 partials, tanh scale.
// ============================================================================
__global__ void kB(const float* __restrict__ alphas, const float* __restrict__ att0) {
  int idx = blockIdx.x * 256 + threadIdx.x;
  if (idx >= KN * KS * 729) return;
  int p = idx % 729;
  int s = (idx / 729) & 1;
  float sum = 0.f;
  #pragma unroll
  for (int ch = 0; ch < 20; ++ch) sum += g_part[ch * 46656 + idx];
  g_att[idx] = tanhf(sum * (1.0f / 6400.0f)) * alphas[s] + att0[s * 729 + p];
}

// ============================================================================
// Kernel C: 448 threads, per (n, 8-t tile), v padded to 28, col = tt*28+v.
// GEMM: 8o x 4col per thread via f32x2; acc = u64[16].
// smem: WB[64][64]@0 | ATT@4096 | consts@5608 | XS@5864 | YB@20200 (138144 B)
// ============================================================================
__device__ __forceinline__ void kc_gemm64(const float* sm, int YB, int og, int cg,
                                          u64* acc) {
  #pragma unroll 4
  for (int k = 0; k < 64; ++k) {
    const float* wr = &sm[k * 64 + og * 8];
    float4 wa = *(const float4*)wr;
    float4 wb = *(const float4*)(wr + 4);
    ulonglong2 y = *(const ulonglong2*)&sm[YB + k * 224 + cg * 4];
    u64 w;
    w = bcast2(wa.x); ffma2(acc[0],  w, y.x); ffma2(acc[1],  w, y.y);
    w = bcast2(wa.y); ffma2(acc[2],  w, y.x); ffma2(acc[3],  w, y.y);
    w = bcast2(wa.z); ffma2(acc[4],  w, y.x); ffma2(acc[5],  w, y.y);
    w = bcast2(wa.w); ffma2(acc[6],  w, y.x); ffma2(acc[7],  w, y.y);
    w = bcast2(wb.x); ffma2(acc[8],  w, y.x); ffma2(acc[9],  w, y.y);
    w = bcast2(wb.y); ffma2(acc[10], w, y.x); ffma2(acc[11], w, y.y);
    w = bcast2(wb.z); ffma2(acc[12], w, y.x); ffma2(acc[13], w, y.y);
    w = bcast2(wb.w); ffma2(acc[14], w, y.x); ffma2(acc[15], w, y.y);
  }
}

__device__ __forceinline__ void kc_y2phase(float* sm, int ATT, int XS, int YB,
                                           int S, int vq, int cq) {
  float a0r[27], a1r[27];
  const int v0 = vq * 2, v1 = vq * 2 + 1;
  #pragma unroll
  for (int u = 0; u < 27; ++u) {
    a0r[u] = sm[ATT + S * 756 + u * 28 + v0];
    a1r[u] = sm[ATT + S * 756 + u * 28 + v1];
  }
  for (int ci = 0; ci < 2; ++ci) {
    const int c = cq * 2 + ci;
    const float* xr = &sm[XS + c * 224];
    #pragma unroll 2
    for (int tt = 0; tt < 8; ++tt) {
      float s0 = 0.f, s1 = 0.f;
      #pragma unroll
      for (int u = 0; u < 27; ++u) {
        float xv = xr[tt * 28 + u];
        s0 += xv * a0r[u]; s1 += xv * a1r[u];
      }
      sm[YB + c * 224 + tt * 28 + v0] = s0;
      sm[YB + c * 224 + tt * 28 + v1] = s1;
    }
  }
}

__global__ void __launch_bounds__(448, 1)
kC(const float* __restrict__ x,
   const float* __restrict__ W_out, const float* __restrict__ b_out,
   const float* __restrict__ gm_out, const float* __restrict__ be_out,
   const float* __restrict__ m_out, const float* __restrict__ v_out,
   const float* __restrict__ W_ff, const float* __restrict__ b_ff,
   const float* __restrict__ gm_ff, const float* __restrict__ be_ff,
   const float* __restrict__ m_ff, const float* __restrict__ v_ff) {
  extern __shared__ float sm[];
  const int ATT = 4096, CAO = 5608, CBO = 5672, CAF = 5736, CBF = 5800;
  const int XS = 5864, YB = 20200;
  const int tid = threadIdx.x;
  const int n = blockIdx.y;
  const int t0 = blockIdx.x * 8;

  for (int j = tid; j < 14336; j += 448) {
    int c = j / 224, col = j % 224, tt = col / 28, v = col % 28;
    sm[XS + j] = (v < 27) ? x[((n * 64 + c) * 400 + t0 + tt) * 27 + v] : 0.f;
  }
  for (int j = tid; j < 1512; j += 448) {
    int s = j / 756, r = j % 756, u = r / 28, v = r % 28;
    sm[ATT + j] = (v < 27) ? g_att[(n * 2 + s) * 729 + u * 27 + v] : 0.f;
  }
  for (int j = tid; j < 4096; j += 448) {
    int k = j >> 6, o = j & 63;
    sm[j] = W_out[o * 128 + k];          // W_out s=0 half, [k][o]
  }
  if (tid < 64) {
    float a = gm_out[tid] * rsqrtf(v_out[tid] + 1e-5f);
    sm[CAO + tid] = a;
    sm[CBO + tid] = (b_out[tid] - m_out[tid]) * a + be_out[tid];
    float af = gm_ff[tid] * rsqrtf(v_ff[tid] + 1e-5f);
    sm[CAF + tid] = af;
    sm[CBF + tid] = (b_ff[tid] - m_ff[tid]) * af + be_ff[tid];
  }
  __syncthreads();

  const int vq = tid / 32, cq = tid % 32;   // y2 mapping (vq 0..13, cq 0..31)
  const int og = tid / 56, cg = tid % 56;   // GEMM mapping (og 0..7, cg 0..55)
  u64 acc[16];
  #pragma unroll
  for (int i = 0; i < 16; ++i) acc[i] = 0ull;

  // s = 0
  kc_y2phase(sm, ATT, XS, YB, 0, vq, cq);
  __syncthreads();
  kc_gemm64(sm, YB, og, cg, acc);
  __syncthreads();

  // s = 1: swap weight half + recompute y2
  for (int j = tid; j < 4096; j += 448) {
    int k = j >> 6, o = j & 63;
    sm[j] = W_out[o * 128 + 64 + k];
  }
  kc_y2phase(sm, ATT, XS, YB, 1, vq, cq);
  __syncthreads();
  kc_gemm64(sm, YB, og, cg, acc);
  __syncthreads();

  // epilogue 1: y3 -> YB ; load W_ff
  for (int j = tid; j < 4096; j += 448) {
    int k = j >> 6, o = j & 63;
    sm[j] = W_ff[o * 64 + k];
  }
  #pragma unroll
  for (int jo = 0; jo < 8; ++jo) {
    int o = og * 8 + jo;
    float a = sm[CAO + o], b = sm[CBO + o];
    float2 A0 = unpk(acc[jo * 2]);
    float2 A1 = unpk(acc[jo * 2 + 1]);
    int base = cg * 4;
    float r0 = lrelu(sm[XS + o * 224 + base + 0] + A0.x * a + b);
    float r1 = lrelu(sm[XS + o * 224 + base + 1] + A0.y * a + b);
    float r2 = lrelu(sm[XS + o * 224 + base + 2] + A1.x * a + b);
    float r3 = lrelu(sm[XS + o * 224 + base + 3] + A1.y * a + b);
    *(float4*)&sm[YB + o * 224 + base] = make_float4(r0, r1, r2, r3);
  }
  #pragma unroll
  for (int i = 0; i < 16; ++i) acc[i] = 0ull;
  __syncthreads();

  kc_gemm64(sm, YB, og, cg, acc);

  // epilogue 2: y4 -> global
  #pragma unroll
  for (int jo = 0; jo < 8; ++jo) {
    int o = og * 8 + jo;
    float a = sm[CAF + o], b = sm[CBF + o];
    float2 A0 = unpk(acc[jo * 2]);
    float2 A1 = unpk(acc[jo * 2 + 1]);
    float rv[4] = {A0.x, A0.y, A1.x, A1.y};
    #pragma unroll
    for (int e = 0; e < 4; ++e) {
      int col = cg * 4 + e;
      int tt = col / 28, v = col % 28;
      if (v < 27) {
        float r = lrelu(sm[XS + o * 224 + col] + rv[e] * a + b);
        g_y4[((long)(n * 64 + o) * 400 + t0 + tt) * 27 + v] = r;
      }
    }
  }
}

// ============================================================================
// Kernel D: temporal conv, 224 threads, 8x8 f32x2 tile, phase-loaded weights.
// smem: WB[96][64]@0 (6144) | YS[64][280]@6144 (17920) | CAT@24064 CBT@24128
// total 24192 f = 96768 B  -> 2 CTAs/SM
// ============================================================================
__global__ void __launch_bounds__(224, 2)
kD(const float* __restrict__ W_t, const float* __restrict__ b_t,
   const float* __restrict__ gm_t, const float* __restrict__ be_t,
   const float* __restrict__ m_t, const float* __restrict__ v_t,
   float* __restrict__ out) {
  extern __shared__ float sm[];
  const int YS = 6144, CAT = 24064, CBT = 24128;
  const int tid = threadIdx.x;
  const int n = blockIdx.y;
  const int t0 = blockIdx.x * 8;

  for (int j = tid; j < 17920; j += 224) {
    int i = j / 280, r = j % 280, tl = r / 28, v = r % 28;
    int t = t0 - 1 + tl;
    sm[YS + j] = (v < 27 && t >= 0 && t < 400)
                 ? g_y4[((long)(n * 64 + i) * 400 + t) * 27 + v] : 0.f;
  }
  if (tid < 64) {
    float a = gm_t[tid] * rsqrtf(v_t[tid] + 1e-5f);
    sm[CAT + tid] = a;
    sm[CBT + tid] = (b_t[tid] - m_t[tid]) * a + be_t[tid];
  }

  const int og = tid / 28, cg = tid % 28;
  u64 acc[32];
  #pragma unroll
  for (int i = 0; i < 32; ++i) acc[i] = 0ull;

  for (int p = 0; p < 2; ++p) {
    __syncthreads();
    for (int j = tid; j < 6144; j += 224) {
      int o = j / 96, r = j % 96;      // r = il*3+kk
      sm[r * 64 + o] = W_t[o * 192 + p * 96 + r];
    }
    __syncthreads();

    #pragma unroll 2
    for (int il = 0; il < 32; ++il) {
      const int i = p * 32 + il;
      #pragma unroll
      for (int kk = 0; kk < 3; ++kk) {
        const float* wr = &sm[(il * 3 + kk) * 64 + og * 8];
        float4 wa = *(const float4*)wr;
        float4 wb = *(const float4*)(wr + 4);
        ulonglong2 ya = *(const ulonglong2*)&sm[YS + i * 280 + kk * 28 + cg * 4];
        ulonglong2 yb = *(const ulonglong2*)&sm[YS + i * 280 + kk * 28 + 112 + cg * 4];
        u64 w;
        w = bcast2(wa.x); ffma2(acc[0],  w, ya.x); ffma2(acc[1],  w, ya.y); ffma2(acc[2],  w, yb.x); ffma2(acc[3],  w, yb.y);
        w = bcast2(wa.y); ffma2(acc[4],  w, ya.x); ffma2(acc[5],  w, ya.y); ffma2(acc[6],  w, yb.x); ffma2(acc[7],  w, yb.y);
        w = bcast2(wa.z); ffma2(acc[8],  w, ya.x); ffma2(acc[9],  w, ya.y); ffma2(acc[10], w, yb.x); ffma2(acc[11], w, yb.y);
        w = bcast2(wa.w); ffma2(acc[12], w, ya.x); ffma2(acc[13], w, ya.y); ffma2(acc[14], w, yb.x); ffma2(acc[15], w, yb.y);
        w = bcast2(wb.x); ffma2(acc[16], w, ya.x); ffma2(acc[17], w, ya.y); ffma2(acc[18], w, yb.x); ffma2(acc[19], w, yb.y);
        w = bcast2(wb.y); ffma2(acc[20], w, ya.x); ffma2(acc[21], w, ya.y); ffma2(acc[22], w, yb.x); ffma2(acc[23], w, yb.y);
        w = bcast2(wb.z); ffma2(acc[24], w, ya.x); ffma2(acc[25], w, ya.y); ffma2(acc[26], w, yb.x); ffma2(acc[27], w, yb.y);
        w = bcast2(wb.w); ffma2(acc[28], w, ya.x); ffma2(acc[29], w, ya.y); ffma2(acc[30], w, yb.x); ffma2(acc[31], w, yb.y);
      }
    }
  }

  #pragma unroll
  for (int jo = 0; jo < 8; ++jo) {
    int o = og * 8 + jo;
    float a = sm[CAT + o], b = sm[CBT + o];
    #pragma unroll
    for (int h = 0; h < 2; ++h) {
      float2 A0 = unpk(acc[jo * 4 + h * 2]);
      float2 A1 = unpk(acc[jo * 4 + h * 2 + 1]);
      float rv[4] = {A0.x, A0.y, A1.x, A1.y};
      int base = h * 112 + cg * 4;
      #pragma unroll
      for (int e = 0; e < 4; ++e) {
        int col = base + e;
        int tt = col / 28, v = col % 28;
        if (v < 27) {
          float y = sm[YS + o * 280 + (tt + 1) * 28 + v];   // residual y4
          float r = lrelu(y + rv[e] * a + b);
          out[((long)(n * 64 + o) * 400 + t0 + tt) * 27 + v] = r;
        }
      }
    }
  }
}

// ============================================================================
extern "C" void kernel_launch(void* const* d_in, const int* in_sizes, int n_in,
                              void* d_out, int out_size) {
  const float* x      = (const float*)d_in[0];
  const float* pe     = (const float*)d_in[1];
  const float* W_in   = (const float*)d_in[2];
  const float* b_in   = (const float*)d_in[3];
  const float* alphas = (const float*)d_in[4];
  const float* att0   = (const float*)d_in[5];
  const float* W_out  = (const float*)d_in[6];
  const float* b_out  = (const float*)d_in[7];
  const float* g_out  = (const float*)d_in[8];
  const float* be_out = (const float*)d_in[9];
  const float* m_out  = (const float*)d_in[10];
  const float* v_out  = (const float*)d_in[11];
  const float* W_ff   = (const float*)d_in[12];
  const float* b_ff   = (const float*)d_in[13];
  const float* g_ff   = (const float*)d_in[14];
  const float* be_ff  = (const float*)d_in[15];
  const float* m_ff   = (const float*)d_in[16];
  const float* v_ff   = (const float*)d_in[17];
  const float* W_t    = (const float*)d_in[18];
  const float* b_t    = (const float*)d_in[19];
  const float* g_t    = (const float*)d_in[20];
  const float* be_t   = (const float*)d_in[21];
  const float* m_t    = (const float*)d_in[22];
  const float* v_t    = (const float*)d_in[23];
  float* out = (float*)d_out;

  cudaFuncSetAttribute(kA, cudaFuncAttributeMaxDynamicSharedMemorySize, 49792);
  cudaFuncSetAttribute(kC, cudaFuncAttributeMaxDynamicSharedMemorySize, 138144);
  cudaFuncSetAttribute(kD, cudaFuncAttributeMaxDynamicSharedMemorySize, 96768);

  kA<<<dim3(20, 2, 32), 224, 49792>>>(x, pe, W_in, b_in);
  kB<<<(KN * KS * 729 + 255) / 256, 256>>>(alphas, att0);
  kC<<<dim3(50, 32), 448, 138144>>>(x, W_out, b_out, g_out, be_out, m_out, v_out,
                                    W_ff, b_ff, g_ff, be_ff, m_ff, v_ff);
  kD<<<dim3(50, 32), 224, 96768>>>(W_t, b_t, g_t, be_t, m_t, v_t, out);
}